// round 17
// baseline (speedup 1.0000x reference)
#include <cuda_runtime.h>
#include <cuda_bf16.h>
#include <cstdint>

// MaxUnpooling2D scatter-add — R5/R9 champion topology with uniform blocks.
//   step s (0..15): every block scatters its slice of batch b=s>>1's stream
//   (REDs predicated on phase h=s&1, targeting the 32MB half-region s) AND
//   zeroes its slice of half-region s+1. 4096 identical blocks -> perfect
//   wave balance (no pure-zero blocks finishing early).
// Cache policy: even steps (first pass over the stream) use default loads so
// the 32MB stream stays L2-resident for the odd step's second pass; odd steps
// use __ldcs (last use, evict-first). L2 live set <= 96MB < 126MB.
// Floor: 33.5M atomic messages; zero-fill and stream traffic hide under it.

static constexpr int B         = 8;
static constexpr int IN_PER_B  = 1 << 22;        // elems per batch input
static constexpr int OUT_PER_B = 1 << 24;        // elems per batch output
static constexpr int HALF_OUT  = OUT_PER_B / 2;  // 2^23 elems, 32 MB

static constexpr int BLOCKS = (IN_PER_B / 4) / 256;  // 4096 uniform blocks
// zero slice: 32MB / 4096 blocks = 8KB/block = 2 float4 per thread

template <bool FIRST_PASS>
__global__ void __launch_bounds__(256)
pipe_half_kernel(const float4* __restrict__ vals4,   // batch stream base
                 const int4*  __restrict__ idx4,
                 float* __restrict__ out_scatter,    // batch output base
                 int phase,                          // 0: idx<2^23, 1: >=
                 float4* __restrict__ out_zero)      // 32MB region or nullptr
{
    int i = blockIdx.x * 256 + threadIdx.x;

    // Stream loads first (long-latency).
    float4 v;
    int4   x;
    if (FIRST_PASS) {            // keep stream resident for the second pass
        v = vals4[i];
        x = idx4[i];
    } else {                     // last use: evict-first
        v = __ldcs(vals4 + i);
        x = __ldcs(idx4 + i);
    }

    // Zero slice: independent of the loads -> issues inside their latency.
    if (out_zero) {
        int zb = blockIdx.x * 512 + threadIdx.x;
        float4 z = make_float4(0.f, 0.f, 0.f, 0.f);
        out_zero[zb]       = z;
        out_zero[zb + 256] = z;
    }

    // Predicated scatter into the 32MB half-region.
    if ((x.x >> 23) == phase) atomicAdd(out_scatter + x.x, v.x);
    if ((x.y >> 23) == phase) atomicAdd(out_scatter + x.y, v.y);
    if ((x.z >> 23) == phase) atomicAdd(out_scatter + x.z, v.z);
    if ((x.w >> 23) == phase) atomicAdd(out_scatter + x.w, v.w);
}

extern "C" void kernel_launch(void* const* d_in, const int* in_sizes, int n_in,
                              void* d_out, int out_size)
{
    const float* vals = (const float*)d_in[0];
    const int*   idx  = (const int*)d_in[1];
    float* out = (float*)d_out;

    // Prologue: zero half-region 0 (32MB) via memset node.
    cudaMemsetAsync(d_out, 0, (size_t)HALF_OUT * sizeof(float));

    // 16 half-steps: step s scatters (b=s>>1, phase=s&1), zeroes region s+1.
    for (int s = 0; s < 2 * B; s++) {
        int b = s >> 1;
        int h = s & 1;
        const float4* v4 = (const float4*)(vals + (size_t)b * IN_PER_B);
        const int4*   x4 = (const int4*)(idx + (size_t)b * IN_PER_B);
        float* out_b = out + (size_t)b * OUT_PER_B;
        float4* zdst = (s + 1 < 2 * B)
                     ? (float4*)(out + (size_t)(s + 1) * HALF_OUT)
                     : nullptr;

        if (h == 0)
            pipe_half_kernel<true><<<BLOCKS, 256>>>(v4, x4, out_b, h, zdst);
        else
            pipe_half_kernel<false><<<BLOCKS, 256>>>(v4, x4, out_b, h, zdst);
    }
}